// round 3
// baseline (speedup 1.0000x reference)
#include <cuda_runtime.h>
#include <stdint.h>

#define NB      8
#define GH      32
#define GW      64
#define FH      128
#define FW      512
#define NFREQ   513
#define NFFT    1024
#define HOP     256
#define NFRAMES 512
#define LSIG    130816      // HOP*(FW-1)
#define TOTAL   131840      // NFFT + HOP*(NFRAMES-1)
#define NSAMP   131072
#define NITER   32
#define MOMC    0.49748743718592964f   // 0.99/1.99

#define SPEC_N  (NB*NFRAMES*NFREQ)     // stored transposed: (b, frame, freq)

// ---------------- device scratch (static, no allocs) ----------------
__device__ float  g_win[NFFT];
__device__ float  g_wsq[TOTAL];
__device__ float2 g_tw512[256];
__device__ float2 g_tw1024[NFREQ];
__device__ float  g_mag[SPEC_N];
__device__ float2 g_ang[SPEC_N];
__device__ float2 g_tp[SPEC_N];
__device__ float  g_frames[NB*NFRAMES*NFFT];
__device__ float  g_sig[NB*TOTAL];
__device__ float  g_maxv[NB];

// ---------------- init: window + twiddles ----------------
__global__ void k_tables() {
    int t = threadIdx.x;
    const double PI = 3.14159265358979323846;
    for (int i = t; i < NFFT; i += blockDim.x) {
        double a = 2.0 * PI * (double)i / (double)NFFT;
        g_win[i] = (float)(0.5 * (1.0 - cos(a)));
    }
    for (int i = t; i < 256; i += blockDim.x) {
        double a = -2.0 * PI * (double)i / 512.0;
        g_tw512[i] = make_float2((float)cos(a), (float)sin(a));
    }
    for (int i = t; i < NFREQ; i += blockDim.x) {
        double a = -2.0 * PI * (double)i / 1024.0;
        g_tw1024[i] = make_float2((float)cos(a), (float)sin(a));
    }
}

__global__ void k_wsq() {
    int t = blockIdx.x * blockDim.x + threadIdx.x;
    if (t >= TOTAL) return;
    int f1 = min(NFRAMES - 1, t >> 8);
    int f0 = (t >= NFFT - 1) ? ((t - (NFFT - 1) + 255) >> 8) : 0;
    float acc = 0.f;
    for (int f = f0; f <= f1; f++) {
        float w = g_win[t - (f << 8)];
        acc += w * w;
    }
    g_wsq[t] = acc;
}

// ---------------- bilinear resizes ----------------
__global__ void k_fullspec(const float* __restrict__ params, float* __restrict__ outFS) {
    int i = blockIdx.x * blockDim.x + threadIdx.x;
    if (i >= NB * FH * FW) return;
    int x = i % FW;
    int y = (i / FW) % FH;
    int b = i / (FW * FH);
    float cy = (y + 0.5f) * ((float)GH / (float)FH) - 0.5f;
    float cx = (x + 0.5f) * ((float)GW / (float)FW) - 0.5f;
    cy = fminf(fmaxf(cy, 0.f), (float)(GH - 1));
    cx = fminf(fmaxf(cx, 0.f), (float)(GW - 1));
    int y0 = (int)cy, x0 = (int)cx;
    int y1 = min(y0 + 1, GH - 1), x1 = min(x0 + 1, GW - 1);
    float wy = cy - (float)y0, wx = cx - (float)x0;
    const float* g = params + b * GH * GW;
    float v00 = g[y0 * GW + x0], v01 = g[y0 * GW + x1];
    float v10 = g[y1 * GW + x0], v11 = g[y1 * GW + x1];
    float v = (v00 * (1.f - wx) + v01 * wx) * (1.f - wy)
            + (v10 * (1.f - wx) + v11 * wx) * wy;
    outFS[i] = v;
}

__global__ void k_mag(const float* __restrict__ fs) {
    int i = blockIdx.x * blockDim.x + threadIdx.x;
    if (i >= SPEC_N) return;
    int k = i % NFREQ;
    int f = (i / NFREQ) % NFRAMES;
    int b = i / (NFREQ * NFRAMES);
    float cy = (k + 0.5f) * ((float)FH / (float)NFREQ) - 0.5f;
    cy = fminf(fmaxf(cy, 0.f), (float)(FH - 1));
    int y0 = (int)cy;
    int y1 = min(y0 + 1, FH - 1);
    float wy = cy - (float)y0;
    float a  = fs[(b * FH + y0) * FW + f];
    float bb = fs[(b * FH + y1) * FW + f];
    float sp = (a * a * 100.f) * (1.f - wy) + (bb * bb * 100.f) * wy;
    g_mag[i] = sqrtf(fmaxf(sp, 0.f));
}

// ---------------- threefry2x32 initial phases ----------------
__device__ __forceinline__ uint32_t rotl32(uint32_t x, int d) {
    return (x << d) | (x >> (32 - d));
}

__device__ __forceinline__ void threefry(uint32_t x0, uint32_t x1,
                                         uint32_t& o0, uint32_t& o1) {
    const uint32_t ks0 = 0u, ks1 = 1u, ks2 = 0u ^ 1u ^ 0x1BD11BDAu;
    const int ra[4] = {13, 15, 26, 6};
    const int rb[4] = {17, 29, 16, 24};
    x0 += ks0; x1 += ks1;
#pragma unroll
    for (int i = 0; i < 4; i++) { x0 += x1; x1 = rotl32(x1, ra[i]); x1 ^= x0; }
    x0 += ks1; x1 += ks2 + 1u;
#pragma unroll
    for (int i = 0; i < 4; i++) { x0 += x1; x1 = rotl32(x1, rb[i]); x1 ^= x0; }
    x0 += ks2; x1 += ks0 + 2u;
#pragma unroll
    for (int i = 0; i < 4; i++) { x0 += x1; x1 = rotl32(x1, ra[i]); x1 ^= x0; }
    x0 += ks0; x1 += ks1 + 3u;
#pragma unroll
    for (int i = 0; i < 4; i++) { x0 += x1; x1 = rotl32(x1, rb[i]); x1 ^= x0; }
    x0 += ks1; x1 += ks2 + 4u;
#pragma unroll
    for (int i = 0; i < 4; i++) { x0 += x1; x1 = rotl32(x1, ra[i]); x1 ^= x0; }
    x0 += ks2; x1 += ks0 + 5u;
    o0 = x0; o1 = x1;
}

// jax_threefry_partitionable=True path (default since jax 0.4.30):
// counter = 64-bit linear iota as (hi, lo) 32-bit words; for bit_width<=32
// the returned bits are bits1 ^ bits2 (XOR of the two threefry output words).
__global__ void k_angles() {
    int e = blockIdx.x * blockDim.x + threadIdx.x;
    const int N = SPEC_N;
    if (e >= N) return;
    uint32_t o0, o1;
    threefry(0u, (uint32_t)e, o0, o1);
    uint32_t bits = o0 ^ o1;
    float u = __uint_as_float((bits >> 9) | 0x3f800000u) - 1.0f;
    float sv, cv;
    sincosf(6.2831853071795864769f * u, &sv, &cv);
    // reference element order is (b, freq, frame); we store (b, frame, freq)
    int f = e % FW;
    int k = (e / FW) % NFREQ;
    int b = e / (FW * NFREQ);
    int idx = (b * NFRAMES + f) * NFREQ + k;
    g_ang[idx] = make_float2(cv, sv);
    g_tp[idx]  = make_float2(0.f, 0.f);
}

// ---------------- 512-point shared-memory complex FFT ----------------
template <bool INV>
__device__ __forceinline__ void fft512(float2* Z, int tid) {
    for (int i = tid; i < 512; i += 128) {
        int j = __brev((unsigned)i) >> 23;
        if (j > i) { float2 t = Z[i]; Z[i] = Z[j]; Z[j] = t; }
    }
    __syncthreads();
    int step = 256;
    for (int len = 2; len <= 512; len <<= 1, step >>= 1) {
        int half = len >> 1;
        for (int p = tid; p < 256; p += 128) {
            int pos = p & (half - 1);
            int i0 = 2 * p - pos;
            int i1 = i0 + half;
            float2 w = g_tw512[pos * step];
            float wy = INV ? -w.y : w.y;
            float2 bb = Z[i1], aa = Z[i0];
            float tx = w.x * bb.x - wy * bb.y;
            float ty = w.x * bb.y + wy * bb.x;
            Z[i0] = make_float2(aa.x + tx, aa.y + ty);
            Z[i1] = make_float2(aa.x - tx, aa.y - ty);
        }
        __syncthreads();
    }
}

// ---------------- ISTFT: spectrum -> windowed frames ----------------
__global__ void k_istft() {
    __shared__ float2 X[NFREQ];
    __shared__ float2 Z[512];
    int bf = blockIdx.x;
    int tid = threadIdx.x;
    const float*  m = g_mag + bf * NFREQ;
    const float2* a = g_ang + bf * NFREQ;
    for (int k = tid; k < NFREQ; k += 128) {
        float mm = m[k];
        float2 aa = a[k];
        X[k] = make_float2(mm * aa.x, mm * aa.y);
    }
    __syncthreads();
    // pack: Z[k] = Ze + i*Zo ;  irfft ignores Im(X[0]), Im(X[512])
    for (int k = tid; k < 512; k += 128) {
        float2 Xk = X[k];
        float2 Xr = X[512 - k];
        if (k == 0) { Xk.y = 0.f; Xr.y = 0.f; }
        float zex = (Xk.x + Xr.x) * 0.5f;
        float zey = (Xk.y - Xr.y) * 0.5f;
        float dx  = (Xk.x - Xr.x) * 0.5f;
        float dy  = (Xk.y + Xr.y) * 0.5f;
        float2 W = g_tw1024[k];
        float zox = dx * W.x + dy * W.y;   // D * conj(W)
        float zoy = dy * W.x - dx * W.y;
        Z[k] = make_float2(zex - zoy, zey + zox);
    }
    __syncthreads();
    fft512<true>(Z, tid);
    float2* out = (float2*)(g_frames + (size_t)bf * NFFT);
    const float inv = 1.0f / 512.0f;
    for (int n = tid; n < 512; n += 128) {
        float2 z = Z[n];
        out[n] = make_float2(z.x * inv * g_win[2 * n],
                             z.y * inv * g_win[2 * n + 1]);
    }
}

// ---------------- overlap-add + wsq division ----------------
__global__ void k_ola() {
    int i = blockIdx.x * blockDim.x + threadIdx.x;
    if (i >= NB * TOTAL) return;
    int t = i % TOTAL;
    int b = i / TOTAL;
    int f1 = min(NFRAMES - 1, t >> 8);
    int f0 = (t >= NFFT - 1) ? ((t - (NFFT - 1) + 255) >> 8) : 0;
    float acc = 0.f;
    const float* fr = g_frames + (size_t)b * NFRAMES * NFFT;
    for (int f = f0; f <= f1; f++) {
        acc += fr[(size_t)f * NFFT + (t - (f << 8))];
    }
    float w = g_wsq[t];
    g_sig[i] = acc / (w > 1e-11f ? w : 1.f);
}

// ---------------- STFT + Griffin-Lim phase update ----------------
__device__ __forceinline__ float ldref(const float* __restrict__ s, int i) {
    int k = i - (NFFT / 2);
    k = (k < 0) ? -k : k;
    if (k >= LSIG) k = 2 * (LSIG - 1) - k;
    return s[(NFFT / 2) + k];
}

__global__ void k_stft() {
    __shared__ float2 Z[512];
    int bf = blockIdx.x;
    int tid = threadIdx.x;
    int b = bf >> 9;
    int f = bf & 511;
    const float* s = g_sig + (size_t)b * TOTAL;
    int base = f << 8;
    for (int n = tid; n < 512; n += 128) {
        int m0 = base + 2 * n;
        Z[n] = make_float2(ldref(s, m0)     * g_win[2 * n],
                           ldref(s, m0 + 1) * g_win[2 * n + 1]);
    }
    __syncthreads();
    fft512<false>(Z, tid);
    float2* ang = g_ang + bf * NFREQ;
    float2* tp  = g_tp  + bf * NFREQ;
    for (int k = tid; k < NFREQ; k += 128) {
        int kk = k & 511;
        float2 Zk = Z[kk];
        float2 Zr = Z[(512 - k) & 511];
        float zex = (Zk.x + Zr.x) * 0.5f;
        float zey = (Zk.y - Zr.y) * 0.5f;
        float dx  = (Zk.x - Zr.x) * 0.5f;
        float dy  = (Zk.y + Zr.y) * 0.5f;
        float zox = dy;            // Zo = D / i
        float zoy = -dx;
        float2 W = g_tw1024[k];
        float Xx = zex + W.x * zox - W.y * zoy;
        float Xy = zey + W.x * zoy + W.y * zox;
        float2 t = tp[k];
        float ax = Xx - MOMC * t.x;
        float ay = Xy - MOMC * t.y;
        float nn = sqrtf(ax * ax + ay * ay) + 1e-16f;
        ang[k] = make_float2(ax / nn, ay / nn);
        tp[k]  = make_float2(Xx, Xy);
    }
}

// ---------------- final normalization ----------------
__global__ void k_max() {
    __shared__ float sm[256];
    int b = blockIdx.x;
    const float* s = g_sig + (size_t)b * TOTAL + (NFFT / 2);
    float m = 0.f;
    for (int t = threadIdx.x; t < LSIG; t += 256) m = fmaxf(m, fabsf(s[t]));
    sm[threadIdx.x] = m;
    __syncthreads();
    for (int o = 128; o; o >>= 1) {
        if (threadIdx.x < o) sm[threadIdx.x] = fmaxf(sm[threadIdx.x], sm[threadIdx.x + o]);
        __syncthreads();
    }
    if (threadIdx.x == 0) g_maxv[b] = fmaxf(sm[0], 1e-8f);
}

__global__ void k_audio(float* __restrict__ out) {
    int i = blockIdx.x * blockDim.x + threadIdx.x;
    if (i >= NB * NSAMP) return;
    int t = i % NSAMP;
    int b = i / NSAMP;
    float v = (t < LSIG) ? g_sig[(size_t)b * TOTAL + (NFFT / 2) + t] : 0.f;
    out[i] = v / g_maxv[b] * 0.9f;
}

// ---------------- launcher ----------------
extern "C" void kernel_launch(void* const* d_in, const int* in_sizes, int n_in,
                              void* d_out, int out_size) {
    const float* params = (const float*)d_in[0];
    float* out = (float*)d_out;
    float* outFS = out + NB * NSAMP;   // tuple order: (audio, full_spec)

    k_tables<<<1, 512>>>();
    k_wsq<<<(TOTAL + 255) / 256, 256>>>();
    k_fullspec<<<(NB * FH * FW + 255) / 256, 256>>>(params, outFS);
    k_mag<<<(SPEC_N + 255) / 256, 256>>>(outFS);
    k_angles<<<(SPEC_N + 255) / 256, 256>>>();

    for (int it = 0; it < NITER; it++) {
        k_istft<<<NB * NFRAMES, 128>>>();
        k_ola<<<(NB * TOTAL + 255) / 256, 256>>>();
        k_stft<<<NB * NFRAMES, 128>>>();
    }
    k_istft<<<NB * NFRAMES, 128>>>();
    k_ola<<<(NB * TOTAL + 255) / 256, 256>>>();

    k_max<<<NB, 256>>>();
    k_audio<<<(NB * NSAMP + 255) / 256, 256>>>(out);
}

// round 4
// speedup vs baseline: 1.9918x; 1.9918x over previous
#include <cuda_runtime.h>
#include <stdint.h>

#define NB      8
#define GH      32
#define GW      64
#define FH      128
#define FW      512
#define NFREQ   513
#define NFFT    1024
#define HOP     256
#define NFRAMES 512
#define LSIG    130816      // HOP*(FW-1)
#define TOTAL   131840      // NFFT + HOP*(NFRAMES-1)
#define NSAMP   131072
#define NITER   32
#define MOMC    0.49748743718592964f   // 0.99/1.99

#define SPEC_N  (NB*NFRAMES*NFREQ)     // stored transposed: (b, frame, freq)

// ---------------- device scratch (static, no allocs) ----------------
__device__ float  g_win[NFFT];
__device__ float  g_iwsq[TOTAL];
__device__ float2 g_twid[512];      // exp(-2*pi*i*j/512)
__device__ float2 g_tw1024[NFREQ];  // exp(-2*pi*i*k/1024)
__device__ float2 g_win2[512];      // (win[2n], win[2n+1])
__device__ float2 g_win2i[512];     // (win[2n]/512, win[2n+1]/512)
__device__ float  g_mag[SPEC_N];
__device__ float2 g_ang[SPEC_N];
__device__ float2 g_tp[SPEC_N];
__device__ float  g_frames[NB*NFRAMES*NFFT];
__device__ float  g_sig[NB*TOTAL];
__device__ float  g_maxv[NB];

// ---------------- init: window + twiddles ----------------
__global__ void k_tables() {
    int t = threadIdx.x;
    const double PI = 3.14159265358979323846;
    for (int i = t; i < NFFT; i += blockDim.x) {
        double a = 2.0 * PI * (double)i / (double)NFFT;
        g_win[i] = (float)(0.5 * (1.0 - cos(a)));
    }
    for (int i = t; i < 512; i += blockDim.x) {
        double a = -2.0 * PI * (double)i / 512.0;
        g_twid[i] = make_float2((float)cos(a), (float)sin(a));
    }
    for (int i = t; i < NFREQ; i += blockDim.x) {
        double a = -2.0 * PI * (double)i / 1024.0;
        g_tw1024[i] = make_float2((float)cos(a), (float)sin(a));
    }
    for (int i = t; i < 512; i += blockDim.x) {
        double a0 = 2.0 * PI * (double)(2 * i) / (double)NFFT;
        double a1 = 2.0 * PI * (double)(2 * i + 1) / (double)NFFT;
        float w0 = (float)(0.5 * (1.0 - cos(a0)));
        float w1 = (float)(0.5 * (1.0 - cos(a1)));
        g_win2[i]  = make_float2(w0, w1);
        g_win2i[i] = make_float2(w0 * (1.f / 512.f), w1 * (1.f / 512.f));
    }
}

__global__ void k_wsq() {
    int t = blockIdx.x * blockDim.x + threadIdx.x;
    if (t >= TOTAL) return;
    int f1 = min(NFRAMES - 1, t >> 8);
    int f0 = (t >= NFFT - 1) ? ((t - (NFFT - 1) + 255) >> 8) : 0;
    float acc = 0.f;
    for (int f = f0; f <= f1; f++) {
        float w = g_win[t - (f << 8)];
        acc += w * w;
    }
    g_iwsq[t] = 1.0f / (acc > 1e-11f ? acc : 1.f);
}

// ---------------- bilinear resizes ----------------
__global__ void k_fullspec(const float* __restrict__ params, float* __restrict__ outFS) {
    int i = blockIdx.x * blockDim.x + threadIdx.x;
    if (i >= NB * FH * FW) return;
    int x = i % FW;
    int y = (i / FW) % FH;
    int b = i / (FW * FH);
    float cy = (y + 0.5f) * ((float)GH / (float)FH) - 0.5f;
    float cx = (x + 0.5f) * ((float)GW / (float)FW) - 0.5f;
    cy = fminf(fmaxf(cy, 0.f), (float)(GH - 1));
    cx = fminf(fmaxf(cx, 0.f), (float)(GW - 1));
    int y0 = (int)cy, x0 = (int)cx;
    int y1 = min(y0 + 1, GH - 1), x1 = min(x0 + 1, GW - 1);
    float wy = cy - (float)y0, wx = cx - (float)x0;
    const float* g = params + b * GH * GW;
    float v00 = g[y0 * GW + x0], v01 = g[y0 * GW + x1];
    float v10 = g[y1 * GW + x0], v11 = g[y1 * GW + x1];
    float v = (v00 * (1.f - wx) + v01 * wx) * (1.f - wy)
            + (v10 * (1.f - wx) + v11 * wx) * wy;
    outFS[i] = v;
}

__global__ void k_mag(const float* __restrict__ fs) {
    int i = blockIdx.x * blockDim.x + threadIdx.x;
    if (i >= SPEC_N) return;
    int k = i % NFREQ;
    int f = (i / NFREQ) % NFRAMES;
    int b = i / (NFREQ * NFRAMES);
    float cy = (k + 0.5f) * ((float)FH / (float)NFREQ) - 0.5f;
    cy = fminf(fmaxf(cy, 0.f), (float)(FH - 1));
    int y0 = (int)cy;
    int y1 = min(y0 + 1, FH - 1);
    float wy = cy - (float)y0;
    float a  = fs[(b * FH + y0) * FW + f];
    float bb = fs[(b * FH + y1) * FW + f];
    float sp = (a * a * 100.f) * (1.f - wy) + (bb * bb * 100.f) * wy;
    g_mag[i] = sqrtf(fmaxf(sp, 0.f));
}

// ---------------- threefry2x32 initial phases ----------------
__device__ __forceinline__ uint32_t rotl32(uint32_t x, int d) {
    return (x << d) | (x >> (32 - d));
}

__device__ __forceinline__ void threefry(uint32_t x0, uint32_t x1,
                                         uint32_t& o0, uint32_t& o1) {
    const uint32_t ks0 = 0u, ks1 = 1u, ks2 = 0u ^ 1u ^ 0x1BD11BDAu;
    const int ra[4] = {13, 15, 26, 6};
    const int rb[4] = {17, 29, 16, 24};
    x0 += ks0; x1 += ks1;
#pragma unroll
    for (int i = 0; i < 4; i++) { x0 += x1; x1 = rotl32(x1, ra[i]); x1 ^= x0; }
    x0 += ks1; x1 += ks2 + 1u;
#pragma unroll
    for (int i = 0; i < 4; i++) { x0 += x1; x1 = rotl32(x1, rb[i]); x1 ^= x0; }
    x0 += ks2; x1 += ks0 + 2u;
#pragma unroll
    for (int i = 0; i < 4; i++) { x0 += x1; x1 = rotl32(x1, ra[i]); x1 ^= x0; }
    x0 += ks0; x1 += ks1 + 3u;
#pragma unroll
    for (int i = 0; i < 4; i++) { x0 += x1; x1 = rotl32(x1, rb[i]); x1 ^= x0; }
    x0 += ks1; x1 += ks2 + 4u;
#pragma unroll
    for (int i = 0; i < 4; i++) { x0 += x1; x1 = rotl32(x1, ra[i]); x1 ^= x0; }
    x0 += ks2; x1 += ks0 + 5u;
    o0 = x0; o1 = x1;
}

// jax_threefry_partitionable=True: bits[i] = xor of the two output words of
// threefry2x32(key=(0,1), counter=(0, i))
__global__ void k_angles() {
    int e = blockIdx.x * blockDim.x + threadIdx.x;
    const int N = SPEC_N;
    if (e >= N) return;
    uint32_t o0, o1;
    threefry(0u, (uint32_t)e, o0, o1);
    uint32_t bits = o0 ^ o1;
    float u = __uint_as_float((bits >> 9) | 0x3f800000u) - 1.0f;
    float sv, cv;
    sincosf(6.2831853071795864769f * u, &sv, &cv);
    // reference element order is (b, freq, frame); we store (b, frame, freq)
    int f = e % FW;
    int k = (e / FW) % NFREQ;
    int b = e / (FW * NFREQ);
    int idx = (b * NFRAMES + f) * NFREQ + k;
    g_ang[idx] = make_float2(cv, sv);
    g_tp[idx]  = make_float2(0.f, 0.f);
}

// ---------------- radix-8 register FFT (512 pt, 64 threads) ----------------
__device__ __forceinline__ float2 cadd(float2 a, float2 b) { return make_float2(a.x + b.x, a.y + b.y); }
__device__ __forceinline__ float2 csub(float2 a, float2 b) { return make_float2(a.x - b.x, a.y - b.y); }
__device__ __forceinline__ float2 cmul(float2 a, float2 b) {
    return make_float2(a.x * b.x - a.y * b.y, a.x * b.y + a.y * b.x);
}
template <bool INV>
__device__ __forceinline__ float2 tw(int j) {
    float2 w = g_twid[j];
    return INV ? make_float2(w.x, -w.y) : w;
}
template <bool INV>
__device__ __forceinline__ float2 mul_mi(float2 a) {  // *(-i) fwd, *(+i) inv
    return INV ? make_float2(-a.y, a.x) : make_float2(a.y, -a.x);
}

template <bool INV>
__device__ __forceinline__ void fft8(float2 v[8]) {
    const float C = 0.70710678118654752440f;
    float2 t0 = cadd(v[0], v[4]), t4 = csub(v[0], v[4]);
    float2 t1 = cadd(v[1], v[5]), t5 = csub(v[1], v[5]);
    float2 t2 = cadd(v[2], v[6]), t6 = csub(v[2], v[6]);
    float2 t3 = cadd(v[3], v[7]), t7 = csub(v[3], v[7]);
    const float s = INV ? C : -C;
    t5 = cmul(t5, make_float2(C, s));
    t6 = mul_mi<INV>(t6);
    t7 = cmul(t7, make_float2(-C, s));
    float2 u0 = cadd(t0, t2), u2 = csub(t0, t2);
    float2 u1 = cadd(t1, t3), u3 = csub(t1, t3);
    float2 u4 = cadd(t4, t6), u6 = csub(t4, t6);
    float2 u5 = cadd(t5, t7), u7 = csub(t5, t7);
    u3 = mul_mi<INV>(u3);
    u7 = mul_mi<INV>(u7);
    v[0] = cadd(u0, u1); v[4] = csub(u0, u1);
    v[2] = cadd(u2, u3); v[6] = csub(u2, u3);
    v[1] = cadd(u4, u5); v[5] = csub(u4, u5);
    v[3] = cadd(u6, u7); v[7] = csub(u6, u7);
}

// In: v[a] = x[64a + tid]. Out: v[h] = X[64h + 8*(tid&7) + (tid>>3)].
// SR/SI: float[576] scratch each, stride-72 per p, conflict-free exchanges.
template <bool INV>
__device__ __forceinline__ void fft512_regs(float2 v[8], int tid, float* SR, float* SI) {
    const int p_ = tid >> 3, q_ = tid & 7;
    fft8<INV>(v);
#pragma unroll
    for (int p = 1; p < 8; p++) v[p] = cmul(v[p], tw<INV>(tid * p));
#pragma unroll
    for (int p = 0; p < 8; p++) { SR[p * 72 + tid] = v[p].x; SI[p * 72 + tid] = v[p].y; }
    __syncthreads();
#pragma unroll
    for (int e = 0; e < 8; e++) {
        int a = p_ * 72 + 8 * e + q_;
        v[e] = make_float2(SR[a], SI[a]);
    }
    fft8<INV>(v);
#pragma unroll
    for (int g = 1; g < 8; g++) v[g] = cmul(v[g], tw<INV>(8 * q_ * g));
    __syncthreads();
#pragma unroll
    for (int g = 0; g < 8; g++) {
        int a = p_ * 72 + 9 * g + q_;
        SR[a] = v[g].x; SI[a] = v[g].y;
    }
    __syncthreads();
#pragma unroll
    for (int f = 0; f < 8; f++) {
        int a = p_ * 72 + 9 * q_ + f;
        v[f] = make_float2(SR[a], SI[a]);
    }
    fft8<INV>(v);
}

// ---------------- ISTFT: spectrum -> windowed frames ----------------
__global__ void __launch_bounds__(64) k_istft() {
    __shared__ float2 X[NFREQ];
    __shared__ float SR[576], SI[576];
    int bf = blockIdx.x;
    int tid = threadIdx.x;
    const float*  m = g_mag + bf * NFREQ;
    const float2* a = g_ang + bf * NFREQ;
    for (int k = tid; k < NFREQ; k += 64) {
        float mm = m[k];
        float2 aa = a[k];
        X[k] = make_float2(mm * aa.x, mm * aa.y);
    }
    __syncthreads();
    float2 v[8];
#pragma unroll
    for (int i = 0; i < 8; i++) {
        int n = 64 * i + tid;
        float2 Xk = X[n];
        float2 Xr = X[512 - n];
        if (n == 0) { Xk.y = 0.f; Xr.y = 0.f; }   // irfft ignores Im(X[0]), Im(X[512])
        float zex = (Xk.x + Xr.x) * 0.5f;
        float zey = (Xk.y - Xr.y) * 0.5f;
        float dx  = (Xk.x - Xr.x) * 0.5f;
        float dy  = (Xk.y + Xr.y) * 0.5f;
        float2 W = g_tw1024[n];
        float zox = dx * W.x + dy * W.y;   // D * conj(W)
        float zoy = dy * W.x - dx * W.y;
        v[i] = make_float2(zex - zoy, zey + zox);
    }
    fft512_regs<true>(v, tid, SR, SI);
    int base_n = 8 * (tid & 7) + (tid >> 3);
    float2* out = (float2*)(g_frames + (size_t)bf * NFFT);
#pragma unroll
    for (int h = 0; h < 8; h++) {
        int n = 64 * h + base_n;
        float2 w = g_win2i[n];
        float2 z = v[h];
        out[n] = make_float2(z.x * w.x, z.y * w.y);
    }
}

// ---------------- overlap-add + wsq division ----------------
__global__ void k_ola() {
    int i = blockIdx.x * blockDim.x + threadIdx.x;
    if (i >= NB * TOTAL) return;
    int t = i % TOTAL;
    int b = i / TOTAL;
    int f1 = min(NFRAMES - 1, t >> 8);
    int f0 = (t >= NFFT - 1) ? ((t - (NFFT - 1) + 255) >> 8) : 0;
    float acc = 0.f;
    const float* fr = g_frames + (size_t)b * NFRAMES * NFFT;
    for (int f = f0; f <= f1; f++) {
        acc += fr[(size_t)f * NFFT + (t - (f << 8))];
    }
    g_sig[i] = acc * g_iwsq[t];
}

// ---------------- STFT + Griffin-Lim phase update ----------------
__device__ __forceinline__ float ldref(const float* __restrict__ s, int i) {
    int k = i - (NFFT / 2);
    k = (k < 0) ? -k : k;
    if (k >= LSIG) k = 2 * (LSIG - 1) - k;
    return s[(NFFT / 2) + k];
}

__global__ void __launch_bounds__(64) k_stft() {
    __shared__ float2 X[512];
    __shared__ float SR[576], SI[576];
    int bf = blockIdx.x;
    int tid = threadIdx.x;
    int b = bf >> 9;
    int f = bf & 511;
    const float* s = g_sig + (size_t)b * TOTAL;
    int base = f << 8;
    float2 v[8];
    if (f >= 2 && f <= 509) {
        const float2* sp = (const float2*)(s + base);   // interior: ldref(s,i) == s[i]
#pragma unroll
        for (int i = 0; i < 8; i++) {
            int n = 64 * i + tid;
            float2 xv = sp[n];
            float2 w = g_win2[n];
            v[i] = make_float2(xv.x * w.x, xv.y * w.y);
        }
    } else {
#pragma unroll
        for (int i = 0; i < 8; i++) {
            int n = 64 * i + tid;
            int m0 = base + 2 * n;
            float2 w = g_win2[n];
            v[i] = make_float2(ldref(s, m0) * w.x, ldref(s, m0 + 1) * w.y);
        }
    }
    fft512_regs<false>(v, tid, SR, SI);
    int base_n = 8 * (tid & 7) + (tid >> 3);
#pragma unroll
    for (int h = 0; h < 8; h++) X[64 * h + base_n] = v[h];
    __syncthreads();
    float2* ang = g_ang + bf * NFREQ;
    float2* tp  = g_tp  + bf * NFREQ;
    for (int k = tid; k < NFREQ; k += 64) {
        int kk = k & 511;
        float2 Zk = X[kk];
        float2 Zr = X[(512 - k) & 511];
        float zex = (Zk.x + Zr.x) * 0.5f;
        float zey = (Zk.y - Zr.y) * 0.5f;
        float dx  = (Zk.x - Zr.x) * 0.5f;
        float dy  = (Zk.y + Zr.y) * 0.5f;
        float zox = dy;            // Zo = D / i
        float zoy = -dx;
        float2 W = g_tw1024[k];
        float Xx = zex + W.x * zox - W.y * zoy;
        float Xy = zey + W.x * zoy + W.y * zox;
        float2 t = tp[k];
        float ax = Xx - MOMC * t.x;
        float ay = Xy - MOMC * t.y;
        float nn = sqrtf(ax * ax + ay * ay) + 1e-16f;
        ang[k] = make_float2(ax / nn, ay / nn);
        tp[k]  = make_float2(Xx, Xy);
    }
}

// ---------------- final normalization ----------------
__global__ void k_max() {
    __shared__ float sm[256];
    int b = blockIdx.x;
    const float* s = g_sig + (size_t)b * TOTAL + (NFFT / 2);
    float m = 0.f;
    for (int t = threadIdx.x; t < LSIG; t += 256) m = fmaxf(m, fabsf(s[t]));
    sm[threadIdx.x] = m;
    __syncthreads();
    for (int o = 128; o; o >>= 1) {
        if (threadIdx.x < o) sm[threadIdx.x] = fmaxf(sm[threadIdx.x], sm[threadIdx.x + o]);
        __syncthreads();
    }
    if (threadIdx.x == 0) g_maxv[b] = fmaxf(sm[0], 1e-8f);
}

__global__ void k_audio(float* __restrict__ out) {
    int i = blockIdx.x * blockDim.x + threadIdx.x;
    if (i >= NB * NSAMP) return;
    int t = i % NSAMP;
    int b = i / NSAMP;
    float v = (t < LSIG) ? g_sig[(size_t)b * TOTAL + (NFFT / 2) + t] : 0.f;
    out[i] = v / g_maxv[b] * 0.9f;
}

// ---------------- launcher ----------------
extern "C" void kernel_launch(void* const* d_in, const int* in_sizes, int n_in,
                              void* d_out, int out_size) {
    const float* params = (const float*)d_in[0];
    float* out = (float*)d_out;
    float* outFS = out + NB * NSAMP;   // tuple order: (audio, full_spec)

    k_tables<<<1, 512>>>();
    k_wsq<<<(TOTAL + 255) / 256, 256>>>();
    k_fullspec<<<(NB * FH * FW + 255) / 256, 256>>>(params, outFS);
    k_mag<<<(SPEC_N + 255) / 256, 256>>>(outFS);
    k_angles<<<(SPEC_N + 255) / 256, 256>>>();

    for (int it = 0; it < NITER; it++) {
        k_istft<<<NB * NFRAMES, 64>>>();
        k_ola<<<(NB * TOTAL + 255) / 256, 256>>>();
        k_stft<<<NB * NFRAMES, 64>>>();
    }
    k_istft<<<NB * NFRAMES, 64>>>();
    k_ola<<<(NB * TOTAL + 255) / 256, 256>>>();

    k_max<<<NB, 256>>>();
    k_audio<<<(NB * NSAMP + 255) / 256, 256>>>(out);
}

// round 6
// speedup vs baseline: 2.2381x; 1.1236x over previous
#include <cuda_runtime.h>
#include <stdint.h>

#define NB      8
#define GH      32
#define GW      64
#define FH      128
#define FW      512
#define NFREQ   513
#define NFFT    1024
#define HOP     256
#define NFRAMES 512
#define LSIG    130816      // HOP*(FW-1)
#define TOTAL   131840      // NFFT + HOP*(NFRAMES-1)
#define NSAMP   131072
#define NITER   32
#define MOMC    0.49748743718592964f   // 0.99/1.99

#define SPEC_N  (NB*NFRAMES*NFREQ)     // stored transposed: (b, frame, freq)

// ---------------- device scratch (static, no allocs) ----------------
__device__ float  g_win[NFFT];
__device__ float  g_iwsq[TOTAL];
__device__ float2 g_twid[512];      // exp(-2*pi*i*j/512)
__device__ float2 g_tw1024[NFREQ];  // exp(-2*pi*i*k/1024)
__device__ float2 g_win2[512];      // (win[2n], win[2n+1])
__device__ float2 g_win2i[512];     // (win[2n]/512, win[2n+1]/512)
__device__ float  g_mag[SPEC_N];
__device__ float2 g_ang[SPEC_N];    // only used for the initial ISTFT
__device__ float2 g_tp[SPEC_N];
__device__ float  g_frames[NB*NFRAMES*NFFT];
__device__ float  g_sig[NB*TOTAL];
__device__ float  g_maxv[NB];

// ---------------- init: window + twiddles ----------------
__global__ void k_tables() {
    int t = threadIdx.x;
    const double PI = 3.14159265358979323846;
    for (int i = t; i < NFFT; i += blockDim.x) {
        double a = 2.0 * PI * (double)i / (double)NFFT;
        g_win[i] = (float)(0.5 * (1.0 - cos(a)));
    }
    for (int i = t; i < 512; i += blockDim.x) {
        double a = -2.0 * PI * (double)i / 512.0;
        g_twid[i] = make_float2((float)cos(a), (float)sin(a));
    }
    for (int i = t; i < NFREQ; i += blockDim.x) {
        double a = -2.0 * PI * (double)i / 1024.0;
        g_tw1024[i] = make_float2((float)cos(a), (float)sin(a));
    }
    for (int i = t; i < 512; i += blockDim.x) {
        double a0 = 2.0 * PI * (double)(2 * i) / (double)NFFT;
        double a1 = 2.0 * PI * (double)(2 * i + 1) / (double)NFFT;
        float w0 = (float)(0.5 * (1.0 - cos(a0)));
        float w1 = (float)(0.5 * (1.0 - cos(a1)));
        g_win2[i]  = make_float2(w0, w1);
        g_win2i[i] = make_float2(w0 * (1.f / 512.f), w1 * (1.f / 512.f));
    }
}

__global__ void k_wsq() {
    int t = blockIdx.x * blockDim.x + threadIdx.x;
    if (t >= TOTAL) return;
    int f1 = min(NFRAMES - 1, t >> 8);
    int f0 = (t >= NFFT - 1) ? ((t - (NFFT - 1) + 255) >> 8) : 0;
    float acc = 0.f;
    for (int f = f0; f <= f1; f++) {
        float w = g_win[t - (f << 8)];
        acc += w * w;
    }
    g_iwsq[t] = 1.0f / (acc > 1e-11f ? acc : 1.f);
}

// ---------------- bilinear resizes ----------------
__global__ void k_fullspec(const float* __restrict__ params, float* __restrict__ outFS) {
    int i = blockIdx.x * blockDim.x + threadIdx.x;
    if (i >= NB * FH * FW) return;
    int x = i % FW;
    int y = (i / FW) % FH;
    int b = i / (FW * FH);
    float cy = (y + 0.5f) * ((float)GH / (float)FH) - 0.5f;
    float cx = (x + 0.5f) * ((float)GW / (float)FW) - 0.5f;
    cy = fminf(fmaxf(cy, 0.f), (float)(GH - 1));
    cx = fminf(fmaxf(cx, 0.f), (float)(GW - 1));
    int y0 = (int)cy, x0 = (int)cx;
    int y1 = min(y0 + 1, GH - 1), x1 = min(x0 + 1, GW - 1);
    float wy = cy - (float)y0, wx = cx - (float)x0;
    const float* g = params + b * GH * GW;
    float v00 = g[y0 * GW + x0], v01 = g[y0 * GW + x1];
    float v10 = g[y1 * GW + x0], v11 = g[y1 * GW + x1];
    float v = (v00 * (1.f - wx) + v01 * wx) * (1.f - wy)
            + (v10 * (1.f - wx) + v11 * wx) * wy;
    outFS[i] = v;
}

__global__ void k_mag(const float* __restrict__ fs) {
    int i = blockIdx.x * blockDim.x + threadIdx.x;
    if (i >= SPEC_N) return;
    int k = i % NFREQ;
    int f = (i / NFREQ) % NFRAMES;
    int b = i / (NFREQ * NFRAMES);
    float cy = (k + 0.5f) * ((float)FH / (float)NFREQ) - 0.5f;
    cy = fminf(fmaxf(cy, 0.f), (float)(FH - 1));
    int y0 = (int)cy;
    int y1 = min(y0 + 1, FH - 1);
    float wy = cy - (float)y0;
    float a  = fs[(b * FH + y0) * FW + f];
    float bb = fs[(b * FH + y1) * FW + f];
    float sp = (a * a * 100.f) * (1.f - wy) + (bb * bb * 100.f) * wy;
    g_mag[i] = sqrtf(fmaxf(sp, 0.f));
}

// ---------------- threefry2x32 initial phases ----------------
__device__ __forceinline__ uint32_t rotl32(uint32_t x, int d) {
    return (x << d) | (x >> (32 - d));
}

__device__ __forceinline__ void threefry(uint32_t x0, uint32_t x1,
                                         uint32_t& o0, uint32_t& o1) {
    const uint32_t ks0 = 0u, ks1 = 1u, ks2 = 0u ^ 1u ^ 0x1BD11BDAu;
    const int ra[4] = {13, 15, 26, 6};
    const int rb[4] = {17, 29, 16, 24};
    x0 += ks0; x1 += ks1;
#pragma unroll
    for (int i = 0; i < 4; i++) { x0 += x1; x1 = rotl32(x1, ra[i]); x1 ^= x0; }
    x0 += ks1; x1 += ks2 + 1u;
#pragma unroll
    for (int i = 0; i < 4; i++) { x0 += x1; x1 = rotl32(x1, rb[i]); x1 ^= x0; }
    x0 += ks2; x1 += ks0 + 2u;
#pragma unroll
    for (int i = 0; i < 4; i++) { x0 += x1; x1 = rotl32(x1, ra[i]); x1 ^= x0; }
    x0 += ks0; x1 += ks1 + 3u;
#pragma unroll
    for (int i = 0; i < 4; i++) { x0 += x1; x1 = rotl32(x1, rb[i]); x1 ^= x0; }
    x0 += ks1; x1 += ks2 + 4u;
#pragma unroll
    for (int i = 0; i < 4; i++) { x0 += x1; x1 = rotl32(x1, ra[i]); x1 ^= x0; }
    x0 += ks2; x1 += ks0 + 5u;
    o0 = x0; o1 = x1;
}

// jax_threefry_partitionable=True: bits[i] = xor of the two output words of
// threefry2x32(key=(0,1), counter=(0, i))
__global__ void k_angles() {
    int e = blockIdx.x * blockDim.x + threadIdx.x;
    const int N = SPEC_N;
    if (e >= N) return;
    uint32_t o0, o1;
    threefry(0u, (uint32_t)e, o0, o1);
    uint32_t bits = o0 ^ o1;
    float u = __uint_as_float((bits >> 9) | 0x3f800000u) - 1.0f;
    float sv, cv;
    sincosf(6.2831853071795864769f * u, &sv, &cv);
    // reference element order is (b, freq, frame); we store (b, frame, freq)
    int f = e % FW;
    int k = (e / FW) % NFREQ;
    int b = e / (FW * NFREQ);
    int idx = (b * NFRAMES + f) * NFREQ + k;
    g_ang[idx] = make_float2(cv, sv);
    g_tp[idx]  = make_float2(0.f, 0.f);
}

// ---------------- radix-8 register FFT (512 pt, 64 threads) ----------------
__device__ __forceinline__ float2 cadd(float2 a, float2 b) { return make_float2(a.x + b.x, a.y + b.y); }
__device__ __forceinline__ float2 csub(float2 a, float2 b) { return make_float2(a.x - b.x, a.y - b.y); }
__device__ __forceinline__ float2 cmul(float2 a, float2 b) {
    return make_float2(a.x * b.x - a.y * b.y, a.x * b.y + a.y * b.x);
}
template <bool INV>
__device__ __forceinline__ float2 tw(int j) {
    float2 w = g_twid[j];
    return INV ? make_float2(w.x, -w.y) : w;
}
template <bool INV>
__device__ __forceinline__ float2 mul_mi(float2 a) {  // *(-i) fwd, *(+i) inv
    return INV ? make_float2(-a.y, a.x) : make_float2(a.y, -a.x);
}

template <bool INV>
__device__ __forceinline__ void fft8(float2 v[8]) {
    const float C = 0.70710678118654752440f;
    float2 t0 = cadd(v[0], v[4]), t4 = csub(v[0], v[4]);
    float2 t1 = cadd(v[1], v[5]), t5 = csub(v[1], v[5]);
    float2 t2 = cadd(v[2], v[6]), t6 = csub(v[2], v[6]);
    float2 t3 = cadd(v[3], v[7]), t7 = csub(v[3], v[7]);
    const float s = INV ? C : -C;
    t5 = cmul(t5, make_float2(C, s));
    t6 = mul_mi<INV>(t6);
    t7 = cmul(t7, make_float2(-C, s));
    float2 u0 = cadd(t0, t2), u2 = csub(t0, t2);
    float2 u1 = cadd(t1, t3), u3 = csub(t1, t3);
    float2 u4 = cadd(t4, t6), u6 = csub(t4, t6);
    float2 u5 = cadd(t5, t7), u7 = csub(t5, t7);
    u3 = mul_mi<INV>(u3);
    u7 = mul_mi<INV>(u7);
    v[0] = cadd(u0, u1); v[4] = csub(u0, u1);
    v[2] = cadd(u2, u3); v[6] = csub(u2, u3);
    v[1] = cadd(u4, u5); v[5] = csub(u4, u5);
    v[3] = cadd(u6, u7); v[7] = csub(u6, u7);
}

// In: v[a] = x[64a + tid]. Out: v[h] = X[64h + 8*(tid&7) + (tid>>3)].
// SR/SI: float[576] scratch each, stride-72 per p, conflict-free exchanges.
template <bool INV>
__device__ __forceinline__ void fft512_regs(float2 v[8], int tid, float* SR, float* SI) {
    const int p_ = tid >> 3, q_ = tid & 7;
    fft8<INV>(v);
#pragma unroll
    for (int p = 1; p < 8; p++) v[p] = cmul(v[p], tw<INV>(tid * p));
#pragma unroll
    for (int p = 0; p < 8; p++) { SR[p * 72 + tid] = v[p].x; SI[p * 72 + tid] = v[p].y; }
    __syncthreads();
#pragma unroll
    for (int e = 0; e < 8; e++) {
        int a = p_ * 72 + 8 * e + q_;
        v[e] = make_float2(SR[a], SI[a]);
    }
    fft8<INV>(v);
#pragma unroll
    for (int g = 1; g < 8; g++) v[g] = cmul(v[g], tw<INV>(8 * q_ * g));
    __syncthreads();
#pragma unroll
    for (int g = 0; g < 8; g++) {
        int a = p_ * 72 + 9 * g + q_;
        SR[a] = v[g].x; SI[a] = v[g].y;
    }
    __syncthreads();
#pragma unroll
    for (int f = 0; f < 8; f++) {
        int a = p_ * 72 + 9 * q_ + f;
        v[f] = make_float2(SR[a], SI[a]);
    }
    fft8<INV>(v);
}

// ---------------- shared helpers: pack spectrum + inverse FFT + frame write ----
// Y[513] holds X (full half-spectrum); writes windowed frame to g_frames[bf].
__device__ __forceinline__ void istft_core(const float2* Y, int bf, int tid,
                                           float* SR, float* SI) {
    float2 v[8];
#pragma unroll
    for (int i = 0; i < 8; i++) {
        int n = 64 * i + tid;
        float2 Xk = Y[n];
        float2 Xr = Y[512 - n];
        if (n == 0) { Xk.y = 0.f; Xr.y = 0.f; }   // irfft ignores Im(X[0]), Im(X[512])
        float zex = (Xk.x + Xr.x) * 0.5f;
        float zey = (Xk.y - Xr.y) * 0.5f;
        float dx  = (Xk.x - Xr.x) * 0.5f;
        float dy  = (Xk.y + Xr.y) * 0.5f;
        float2 W = g_tw1024[n];
        float zox = dx * W.x + dy * W.y;   // D * conj(W)
        float zoy = dy * W.x - dx * W.y;
        v[i] = make_float2(zex - zoy, zey + zox);
    }
    fft512_regs<true>(v, tid, SR, SI);
    int base_n = 8 * (tid & 7) + (tid >> 3);
    float2* out = (float2*)(g_frames + (size_t)bf * NFFT);
#pragma unroll
    for (int h = 0; h < 8; h++) {
        int n = 64 * h + base_n;
        float2 w = g_win2i[n];
        float2 z = v[h];
        out[n] = make_float2(z.x * w.x, z.y * w.y);
    }
}

// ---------------- initial ISTFT (uses g_ang from k_angles) ----------------
__global__ void __launch_bounds__(64) k_istft0() {
    __shared__ float2 Y[NFREQ];
    __shared__ float SR[576], SI[576];
    int bf = blockIdx.x;
    int tid = threadIdx.x;
    const float*  m = g_mag + bf * NFREQ;
    const float2* a = g_ang + bf * NFREQ;
    for (int k = tid; k < NFREQ; k += 64) {
        float mm = m[k];
        float2 aa = a[k];
        Y[k] = make_float2(mm * aa.x, mm * aa.y);
    }
    __syncthreads();
    istft_core(Y, bf, tid, SR, SI);
}

// ---------------- overlap-add + wsq division ----------------
__global__ void k_ola() {
    int i = blockIdx.x * blockDim.x + threadIdx.x;
    if (i >= NB * TOTAL) return;
    int t = i % TOTAL;
    int b = i / TOTAL;
    int f1 = min(NFRAMES - 1, t >> 8);
    int f0 = (t >= NFFT - 1) ? ((t - (NFFT - 1) + 255) >> 8) : 0;
    float acc = 0.f;
    const float* fr = g_frames + (size_t)b * NFRAMES * NFFT;
    for (int f = f0; f <= f1; f++) {
        acc += fr[(size_t)f * NFFT + (t - (f << 8))];
    }
    g_sig[i] = acc * g_iwsq[t];
}

// ---------------- fused STFT + phase update + ISTFT ----------------
__device__ __forceinline__ float ldref(const float* __restrict__ s, int i) {
    int k = i - (NFFT / 2);
    k = (k < 0) ? -k : k;
    if (k >= LSIG) k = 2 * (LSIG - 1) - k;
    return s[(NFFT / 2) + k];
}

__global__ void __launch_bounds__(64) k_fused() {
    __shared__ float2 X[512];     // packed forward FFT output
    __shared__ float2 Y[NFREQ];   // mag * new angles
    __shared__ float SR[576], SI[576];
    int bf = blockIdx.x;
    int tid = threadIdx.x;
    int b = bf >> 9;
    int f = bf & 511;
    const float* s = g_sig + (size_t)b * TOTAL;
    int base = f << 8;
    float2 v[8];
    if (f >= 2 && f <= 509) {
        const float2* sp = (const float2*)(s + base);   // interior: ldref(s,i) == s[i]
#pragma unroll
        for (int i = 0; i < 8; i++) {
            int n = 64 * i + tid;
            float2 xv = sp[n];
            float2 w = g_win2[n];
            v[i] = make_float2(xv.x * w.x, xv.y * w.y);
        }
    } else {
#pragma unroll
        for (int i = 0; i < 8; i++) {
            int n = 64 * i + tid;
            int m0 = base + 2 * n;
            float2 w = g_win2[n];
            v[i] = make_float2(ldref(s, m0) * w.x, ldref(s, m0 + 1) * w.y);
        }
    }
    fft512_regs<false>(v, tid, SR, SI);
    int base_n = 8 * (tid & 7) + (tid >> 3);
#pragma unroll
    for (int h = 0; h < 8; h++) X[64 * h + base_n] = v[h];
    __syncthreads();
    // unpack rebuilt spectrum, GL phase update, Y = mag * new angle
    const float* m = g_mag + bf * NFREQ;
    float2* tp = g_tp + bf * NFREQ;
    for (int k = tid; k < NFREQ; k += 64) {
        int kk = k & 511;
        float2 Zk = X[kk];
        float2 Zr = X[(512 - k) & 511];
        float zex = (Zk.x + Zr.x) * 0.5f;
        float zey = (Zk.y - Zr.y) * 0.5f;
        float dx  = (Zk.x - Zr.x) * 0.5f;
        float dy  = (Zk.y + Zr.y) * 0.5f;
        float zox = dy;            // Zo = D / i
        float zoy = -dx;
        float2 W = g_tw1024[k];
        float Xx = zex + W.x * zox - W.y * zoy;
        float Xy = zey + W.x * zoy + W.y * zox;
        float2 t = tp[k];
        float ax = Xx - MOMC * t.x;
        float ay = Xy - MOMC * t.y;
        float nn = sqrtf(ax * ax + ay * ay) + 1e-16f;
        float mm = m[k];
        Y[k] = make_float2(mm * ax / nn, mm * ay / nn);
        tp[k] = make_float2(Xx, Xy);
    }
    __syncthreads();
    istft_core(Y, bf, tid, SR, SI);
}

// ---------------- final normalization ----------------
__global__ void k_max() {
    __shared__ float sm[256];
    int b = blockIdx.x;
    const float* s = g_sig + (size_t)b * TOTAL + (NFFT / 2);
    float m = 0.f;
    for (int t = threadIdx.x; t < LSIG; t += 256) m = fmaxf(m, fabsf(s[t]));
    sm[threadIdx.x] = m;
    __syncthreads();
    for (int o = 128; o; o >>= 1) {
        if (threadIdx.x < o) sm[threadIdx.x] = fmaxf(sm[threadIdx.x], sm[threadIdx.x + o]);
        __syncthreads();
    }
    if (threadIdx.x == 0) g_maxv[b] = fmaxf(sm[0], 1e-8f);
}

__global__ void k_audio(float* __restrict__ out) {
    int i = blockIdx.x * blockDim.x + threadIdx.x;
    if (i >= NB * NSAMP) return;
    int t = i % NSAMP;
    int b = i / NSAMP;
    float v = (t < LSIG) ? g_sig[(size_t)b * TOTAL + (NFFT / 2) + t] : 0.f;
    out[i] = v / g_maxv[b] * 0.9f;
}

// ---------------- launcher ----------------
extern "C" void kernel_launch(void* const* d_in, const int* in_sizes, int n_in,
                              void* d_out, int out_size) {
    const float* params = (const float*)d_in[0];
    float* out = (float*)d_out;
    float* outFS = out + NB * NSAMP;   // tuple order: (audio, full_spec)

    k_tables<<<1, 512>>>();
    k_wsq<<<(TOTAL + 255) / 256, 256>>>();
    k_fullspec<<<(NB * FH * FW + 255) / 256, 256>>>(params, outFS);
    k_mag<<<(SPEC_N + 255) / 256, 256>>>(outFS);
    k_angles<<<(SPEC_N + 255) / 256, 256>>>();

    k_istft0<<<NB * NFRAMES, 64>>>();
    k_ola<<<(NB * TOTAL + 255) / 256, 256>>>();
    for (int it = 0; it < NITER; it++) {
        k_fused<<<NB * NFRAMES, 64>>>();
        k_ola<<<(NB * TOTAL + 255) / 256, 256>>>();
    }

    k_max<<<NB, 256>>>();
    k_audio<<<(NB * NSAMP + 255) / 256, 256>>>(out);
}